// round 3
// baseline (speedup 1.0000x reference)
#include <cuda_runtime.h>
#include <math.h>

#define NBATCH 4
#define NFQ    300
#define QDIM   512
#define HIDDEN 512
#define NHEADS 8
#define HD     64
#define NPIX   6400
#define NORMF  0.125f
#define MROWS  (NBATCH*NFQ)          // 1200
#define OROWS  (NFQ*NHEADS)          // 2400

// ---- scratch (static device globals; no runtime allocation) ----
__device__ float g_qh[MROWS*HIDDEN];                       // 2.4 MB
__device__ float g_kp[(size_t)NBATCH*HIDDEN*NPIX];         // 52.4 MB
#define CBLK_PER_BATCH 2000                                // 8 heads * 5 mtiles * 50 ntiles
__device__ float g_pmax[NBATCH*CBLK_PER_BATCH];
__device__ float g_psum[NBATCH*CBLK_PER_BATCH];
__device__ float g_M[NBATCH];
__device__ float g_invZ[NBATCH];

// ============================================================
// Kernel A: q projection.  qh[r,e] = (sum_d q[r,d]*qw[e,d] + qb[e]) * NORMF
// r in [0,1200). BM=BN=64, BK=16, 256 thr, 4x4 micro.
// ============================================================
__global__ void qproj_kernel(const float* __restrict__ q,
                             const float* __restrict__ qw,
                             const float* __restrict__ qb) {
    const int BM = 64, BN = 64, BK = 16;
    __shared__ float As[BK][BM];
    __shared__ float Bs[BK][BN];
    int t  = threadIdx.x;
    int tx = t & 15, ty = t >> 4;
    int m0 = blockIdx.y * BM;
    int n0 = blockIdx.x * BN;
    int lrow = t >> 2, lseg = t & 3;   // 64 rows x 4 segs(of float4)

    float acc[4][4] = {};
    for (int k0 = 0; k0 < QDIM; k0 += BK) {
        float4 av = make_float4(0.f, 0.f, 0.f, 0.f);
        int gm = m0 + lrow;
        if (gm < MROWS)
            av = *(const float4*)(q + (size_t)gm*QDIM + k0 + lseg*4);
        float4 bv = *(const float4*)(qw + (size_t)(n0 + lrow)*QDIM + k0 + lseg*4);
        __syncthreads();
        As[lseg*4+0][lrow]=av.x; As[lseg*4+1][lrow]=av.y;
        As[lseg*4+2][lrow]=av.z; As[lseg*4+3][lrow]=av.w;
        Bs[lseg*4+0][lrow]=bv.x; Bs[lseg*4+1][lrow]=bv.y;
        Bs[lseg*4+2][lrow]=bv.z; Bs[lseg*4+3][lrow]=bv.w;
        __syncthreads();
#pragma unroll
        for (int k = 0; k < BK; k++) {
            float a[4], b[4];
            *(float4*)a = *(float4*)&As[k][ty*4];
            *(float4*)b = *(float4*)&Bs[k][tx*4];
#pragma unroll
            for (int i = 0; i < 4; i++)
#pragma unroll
                for (int j = 0; j < 4; j++)
                    acc[i][j] += a[i]*b[j];
        }
    }
#pragma unroll
    for (int i = 0; i < 4; i++) {
        int gm = m0 + ty*4 + i;
        if (gm >= MROWS) continue;
#pragma unroll
        for (int j = 0; j < 4; j++) {
            int e = n0 + tx*4 + j;
            g_qh[(size_t)gm*HIDDEN + e] = (acc[i][j] + qb[e]) * NORMF;
        }
    }
}

// ============================================================
// Kernel B: k projection (1x1 conv).  kp[b,e,p] = sum_d kw[e,d]*k[b,d,p] + kb[e]
// Per batch: [512,512] @ [512,6400]. BM=BN=128, BK=8, 256 thr, 8x8 micro.
// ============================================================
__global__ void kproj_kernel(const float* __restrict__ kin,
                             const float* __restrict__ kw,
                             const float* __restrict__ kb) {
    const int BM = 128, BN = 128, BK = 8;
    __shared__ float As[BK][BM];
    __shared__ float Bs[BK][BN];
    int b = blockIdx.z;
    const float* K = kin + (size_t)b*HIDDEN*NPIX;
    float* C = g_kp + (size_t)b*HIDDEN*NPIX;
    int e0 = blockIdx.y * BM;
    int p0 = blockIdx.x * BN;
    int t  = threadIdx.x;
    int tx = t & 15, ty = t >> 4;
    int arow = t >> 1, aseg = t & 1;   // 128 rows x 2 segs
    int brow = t >> 5, bseg = t & 31;  // 8 rows x 32 segs

    float acc[8][8] = {};
    for (int k0 = 0; k0 < QDIM; k0 += BK) {
        float4 av = *(const float4*)(kw + (size_t)(e0 + arow)*QDIM + k0 + aseg*4);
        float4 bv = *(const float4*)(K + (size_t)(k0 + brow)*NPIX + p0 + bseg*4);
        __syncthreads();
        As[aseg*4+0][arow]=av.x; As[aseg*4+1][arow]=av.y;
        As[aseg*4+2][arow]=av.z; As[aseg*4+3][arow]=av.w;
        *(float4*)&Bs[brow][bseg*4] = bv;
        __syncthreads();
#pragma unroll
        for (int k = 0; k < BK; k++) {
            float a[8], bb[8];
            *(float4*)(a)   = *(float4*)&As[k][ty*8];
            *(float4*)(a+4) = *(float4*)&As[k][ty*8+4];
            *(float4*)(bb)   = *(float4*)&Bs[k][tx*8];
            *(float4*)(bb+4) = *(float4*)&Bs[k][tx*8+4];
#pragma unroll
            for (int i = 0; i < 8; i++)
#pragma unroll
                for (int j = 0; j < 8; j++)
                    acc[i][j] += a[i]*bb[j];
        }
    }
#pragma unroll
    for (int i = 0; i < 8; i++) {
        int e = e0 + ty*8 + i;
        float bias = kb[e];
        float4 o0 = make_float4(acc[i][0]+bias, acc[i][1]+bias, acc[i][2]+bias, acc[i][3]+bias);
        float4 o1 = make_float4(acc[i][4]+bias, acc[i][5]+bias, acc[i][6]+bias, acc[i][7]+bias);
        *(float4*)(C + (size_t)e*NPIX + p0 + tx*8)     = o0;
        *(float4*)(C + (size_t)e*NPIX + p0 + tx*8 + 4) = o1;
    }
}

// ============================================================
// Kernel C: scores + mask + per-block softmax stats.
// For (b, head n): S[f,p] = sum_c qh[b,f,n*64+c] * kp[b,n*64+c,p]
// Writes masked scores into d_out, emits per-block (max, sumexp).
// BM=64(f), BN=128(p), BK=16, K=64. 256 thr, 4x8 micro.
// grid: x=50 ptiles, y=5 mtiles, z=32 (b*8+n)
// ============================================================
__global__ void scores_kernel(const int* __restrict__ mask,
                              float* __restrict__ out) {
    const int BM = 64, BN = 128, BK = 16;
    __shared__ float As[BK][BM];
    __shared__ float Bs[BK][BN];
    __shared__ float rm[256];
    __shared__ float rs[256];
    int bh = blockIdx.z;
    int b = bh >> 3, n = bh & 7;
    int m0 = blockIdx.y * BM;
    int p0 = blockIdx.x * BN;
    int t  = threadIdx.x;
    int tx = t & 15, ty = t >> 4;
    const float* A  = g_qh + (size_t)(b*NFQ)*HIDDEN + n*HD;            // [f, c] stride HIDDEN
    const float* Bp = g_kp + ((size_t)b*HIDDEN + n*HD)*NPIX;           // [c, p] stride NPIX
    int arow = t >> 2, aseg = t & 3;   // 64 rows x 4 segs
    int i1 = t + 256;
    int r0 = t >> 5,  s0 = t & 31;
    int r1 = i1 >> 5, s1 = i1 & 31;

    float acc[4][8] = {};
    for (int k0 = 0; k0 < HD; k0 += BK) {
        float4 av = make_float4(0.f, 0.f, 0.f, 0.f);
        int gf = m0 + arow;
        if (gf < NFQ)
            av = *(const float4*)(A + (size_t)gf*HIDDEN + k0 + aseg*4);
        float4 bv0 = *(const float4*)(Bp + (size_t)(k0+r0)*NPIX + p0 + s0*4);
        float4 bv1 = *(const float4*)(Bp + (size_t)(k0+r1)*NPIX + p0 + s1*4);
        __syncthreads();
        As[aseg*4+0][arow]=av.x; As[aseg*4+1][arow]=av.y;
        As[aseg*4+2][arow]=av.z; As[aseg*4+3][arow]=av.w;
        *(float4*)&Bs[r0][s0*4] = bv0;
        *(float4*)&Bs[r1][s1*4] = bv1;
        __syncthreads();
#pragma unroll
        for (int k = 0; k < BK; k++) {
            float a[4], bb[8];
            *(float4*)a      = *(float4*)&As[k][ty*4];
            *(float4*)(bb)   = *(float4*)&Bs[k][tx*8];
            *(float4*)(bb+4) = *(float4*)&Bs[k][tx*8+4];
#pragma unroll
            for (int i = 0; i < 4; i++)
#pragma unroll
                for (int j = 0; j < 8; j++)
                    acc[i][j] += a[i]*bb[j];
        }
    }

    // epilogue: mask, store, local stats
    const int* mrow = mask + (size_t)b*NPIX;
    int mk[8];
#pragma unroll
    for (int j = 0; j < 8; j++) mk[j] = mrow[p0 + tx*8 + j];

    float tmax = -INFINITY;
#pragma unroll
    for (int i = 0; i < 4; i++) {
        int f = m0 + ty*4 + i;
        if (f >= NFQ) continue;
        size_t rowbase = ((size_t)b*OROWS + (size_t)f*NHEADS + n) * NPIX;
#pragma unroll
        for (int j = 0; j < 8; j++) {
            float v = mk[j] ? -INFINITY : acc[i][j];
            out[rowbase + p0 + tx*8 + j] = v;
            tmax = fmaxf(tmax, v);
        }
    }
    float tsum = 0.f;
    if (tmax > -1e37f) {
#pragma unroll
        for (int i = 0; i < 4; i++) {
            int f = m0 + ty*4 + i;
            if (f >= NFQ) continue;
#pragma unroll
            for (int j = 0; j < 8; j++)
                if (!mk[j]) tsum += __expf(acc[i][j] - tmax);
        }
    }
    rm[t] = tmax; rs[t] = tsum;
    __syncthreads();
    for (int s = 128; s > 0; s >>= 1) {
        if (t < s) {
            float m1 = rm[t], s1v = rs[t];
            float m2 = rm[t+s], s2v = rs[t+s];
            float M = fmaxf(m1, m2);
            float sum = 0.f;
            if (m1 > -1e37f) sum += s1v * __expf(m1 - M);
            if (m2 > -1e37f) sum += s2v * __expf(m2 - M);
            rm[t] = M; rs[t] = sum;
        }
        __syncthreads();
    }
    if (t == 0) {
        int pidx = (int)blockIdx.z * 250 + (int)blockIdx.y * 50 + (int)blockIdx.x;
        g_pmax[pidx] = rm[0];
        g_psum[pidx] = rs[0];
    }
}

// ============================================================
// Kernel D: combine per-block stats into per-batch (M, 1/Z).
// ============================================================
__global__ void combine_kernel() {
    __shared__ float rm[256];
    __shared__ float rs[256];
    int b = blockIdx.x, t = threadIdx.x;
    float m = -INFINITY, s = 0.f;
    for (int i = t; i < CBLK_PER_BATCH; i += 256) {
        float m2 = g_pmax[b*CBLK_PER_BATCH + i];
        float s2 = g_psum[b*CBLK_PER_BATCH + i];
        float M = fmaxf(m, m2);
        float ns = 0.f;
        if (m  > -1e37f) ns += s  * __expf(m  - M);
        if (m2 > -1e37f) ns += s2 * __expf(m2 - M);
        m = M; s = ns;
    }
    rm[t] = m; rs[t] = s;
    __syncthreads();
    for (int st = 128; st > 0; st >>= 1) {
        if (t < st) {
            float m1 = rm[t], s1v = rs[t];
            float m2 = rm[t+st], s2v = rs[t+st];
            float M = fmaxf(m1, m2);
            float sum = 0.f;
            if (m1 > -1e37f) sum += s1v * __expf(m1 - M);
            if (m2 > -1e37f) sum += s2v * __expf(m2 - M);
            rm[t] = M; rs[t] = sum;
        }
        __syncthreads();
    }
    if (t == 0) {
        g_M[b] = rm[0];
        g_invZ[b] = 1.0f / rs[0];
    }
}

// ============================================================
// Kernel E: normalize in place.  out = exp(s - M_b) / Z_b  (masked -> 0)
// ============================================================
__global__ void norm_kernel(float* __restrict__ out) {
    const int VPB = (NFQ*NHEADS*NPIX) / 4;   // float4 per batch = 3,840,000
    const int NV  = NBATCH * VPB;
    float4* o = (float4*)out;
    for (int i = blockIdx.x*blockDim.x + threadIdx.x; i < NV;
         i += gridDim.x*blockDim.x) {
        int b = i / VPB;
        float M  = g_M[b];
        float iz = g_invZ[b];
        float4 v = o[i];
        v.x = (v.x > -1e37f) ? __expf(v.x - M)*iz : 0.f;
        v.y = (v.y > -1e37f) ? __expf(v.y - M)*iz : 0.f;
        v.z = (v.z > -1e37f) ? __expf(v.z - M)*iz : 0.f;
        v.w = (v.w > -1e37f) ? __expf(v.w - M)*iz : 0.f;
        o[i] = v;
    }
}

// ============================================================
extern "C" void kernel_launch(void* const* d_in, const int* in_sizes, int n_in,
                              void* d_out, int out_size) {
    const float* q    = (const float*)d_in[0];   // [4,300,512]
    const float* k    = (const float*)d_in[1];   // [4,512,80,80]
    const int*   mask = (const int*)  d_in[2];   // [4,80,80] nonzero = masked
    const float* qw   = (const float*)d_in[3];   // [512,512]
    const float* qb   = (const float*)d_in[4];   // [512]
    const float* kw   = (const float*)d_in[5];   // [512,512]
    const float* kb   = (const float*)d_in[6];   // [512]
    float* out = (float*)d_out;                  // [4,1,2400,80,80]

    qproj_kernel <<<dim3(8, 19),     256>>>(q, qw, qb);
    kproj_kernel <<<dim3(50, 4, 4),  256>>>(k, kw, kb);
    scores_kernel<<<dim3(50, 5, 32), 256>>>(mask, out);
    combine_kernel<<<4, 256>>>();
    norm_kernel  <<<2048, 256>>>(out);
}

// round 6
// speedup vs baseline: 2.7790x; 2.7790x over previous
#include <cuda_runtime.h>
#include <cuda_bf16.h>
#include <stdint.h>
#include <math.h>

#define NBATCH 4
#define NFQ    300
#define QDIM   512
#define HIDDEN 512
#define NHEADS 8
#define HD     64
#define NPIX   6400
#define NORMF  0.125f
#define MROWS  (NBATCH*NFQ)          // 1200
#define OROWS  (NFQ*NHEADS)          // 2400
#define CBLK_PER_BATCH 1200          // 8 heads * 3 mtiles * 50 ntiles

// ---------------- static device scratch ----------------
__device__ __nv_bfloat16 g_kw_hi[HIDDEN*QDIM];
__device__ __nv_bfloat16 g_kw_lo[HIDDEN*QDIM];
__device__ __nv_bfloat16 g_kt_hi[(size_t)NBATCH*NPIX*QDIM];   // [b][p][d]
__device__ __nv_bfloat16 g_kt_lo[(size_t)NBATCH*NPIX*QDIM];
__device__ __nv_bfloat16 g_qht_hi[NBATCH*NHEADS*NFQ*HD];      // [b][n][f][c]
__device__ __nv_bfloat16 g_qht_lo[NBATCH*NHEADS*NFQ*HD];
__device__ __nv_bfloat16 g_kpt_hi[(size_t)NBATCH*NHEADS*NPIX*HD]; // [b][n][p][c]
__device__ __nv_bfloat16 g_kpt_lo[(size_t)NBATCH*NHEADS*NPIX*HD];
__device__ float g_pmax[NBATCH*CBLK_PER_BATCH];
__device__ float g_psum[NBATCH*CBLK_PER_BATCH];
__device__ float g_M[NBATCH];
__device__ float g_invZ[NBATCH];

// ---------------- smem layout (bytes into dynamic smem) ----------------
// 2-stage tiles: A/B 16KB each
#define STG_A0 0u
#define STG_B0 16384u
#define STG_A1 32768u
#define STG_B1 49152u
#define C_OFF  0u                       // fp32 [128][132] overlay after compute: 67584 B
#define KB_OFF 67584u                   // kproj: bias tile (512 B)
#define RM_OFF 67584u                   // scores: reduce max (1024 B)
#define RS_OFF 68608u                   // scores: reduce sum (1024 B)
#define MK_OFF 69632u                   // scores: mask tile (512 B)
#define SMEM_SZ 70656u

// ---------------- ptx helpers ----------------
__device__ __forceinline__ uint32_t smem_u32(const void* p) {
    uint32_t a;
    asm("{ .reg .u64 t; cvta.to.shared.u64 t, %1; cvt.u32.u64 %0, t; }" : "=r"(a) : "l"(p));
    return a;
}
__device__ __forceinline__ void cpa16(uint32_t dst, const void* src, int srcbytes) {
    asm volatile("cp.async.cg.shared.global [%0], [%1], 16, %2;"
                 :: "r"(dst), "l"(src), "r"(srcbytes) : "memory");
}
#define CP_COMMIT() asm volatile("cp.async.commit_group;" ::: "memory")
#define CP_WAIT1()  asm volatile("cp.async.wait_group 1;" ::: "memory")
#define CP_WAIT0()  asm volatile("cp.async.wait_group 0;" ::: "memory")

__device__ __forceinline__ void ldm_x4(uint32_t& r0, uint32_t& r1, uint32_t& r2, uint32_t& r3,
                                       uint32_t addr) {
    asm volatile("ldmatrix.sync.aligned.m8n8.x4.shared.b16 {%0,%1,%2,%3}, [%4];"
                 : "=r"(r0), "=r"(r1), "=r"(r2), "=r"(r3) : "r"(addr));
}
__device__ __forceinline__ void mma_bf16(float* c, uint32_t a0, uint32_t a1, uint32_t a2,
                                         uint32_t a3, uint32_t b0, uint32_t b1) {
    asm volatile("mma.sync.aligned.m16n8k16.row.col.f32.bf16.bf16.f32 "
        "{%0,%1,%2,%3}, {%4,%5,%6,%7}, {%8,%9}, {%0,%1,%2,%3};"
        : "+f"(c[0]), "+f"(c[1]), "+f"(c[2]), "+f"(c[3])
        : "r"(a0), "r"(a1), "r"(a2), "r"(a3), "r"(b0), "r"(b1));
}
__device__ __forceinline__ uint32_t sw128(uint32_t off) { return off ^ ((off >> 3) & 0x70); }

__device__ __forceinline__ void split_bf16(float x, __nv_bfloat16& h, __nv_bfloat16& l) {
    h = __float2bfloat16(x);
    l = __float2bfloat16(x - __bfloat162float(h));
}

// ---- load a [128 rows x 64 bf16] tile into swizzled smem via cp.async ----
// thread t: row = t>>1, half = t&1 (32 cols), 4 x 16B. rows >= nrows zero-filled.
__device__ __forceinline__ void load_tile64(uint32_t dst, const __nv_bfloat16* base,
                                            int rowstride, int k0, int t, int nrows) {
    int r = t >> 1, half = t & 1;
    int rc = (r < nrows) ? r : 0;
    const char* src = (const char*)(base + (size_t)rc*rowstride + k0 + half*32);
    int ok = (r < nrows) ? 16 : 0;
#pragma unroll
    for (int j = 0; j < 4; j++) {
        uint32_t off = sw128((uint32_t)(r*128 + half*64 + j*16));
        cpa16(dst + off, src + j*16, ok);
    }
}

// ---- one 64-wide K chunk of 128x128 HMMA (warp tile 64x32) ----
__device__ __forceinline__ void compute_chunk(uint32_t aBase, uint32_t bBase,
                                              int wm, int wn, int lane,
                                              float acc[4][4][4]) {
#pragma unroll
    for (int kk = 0; kk < 64; kk += 16) {
        uint32_t a[4][4];
#pragma unroll
        for (int mf = 0; mf < 4; mf++) {
            int row  = wm*64 + mf*16 + (lane & 15);
            int kcol = kk + ((lane >> 4) << 3);
            uint32_t off = sw128((uint32_t)(row*128 + kcol*2));
            ldm_x4(a[mf][0], a[mf][1], a[mf][2], a[mf][3], aBase + off);
        }
        uint32_t b[4][2];
#pragma unroll
        for (int g = 0; g < 2; g++) {
            int nrow = wn*32 + g*16 + ((lane >> 4) << 3) + (lane & 7);
            int kcol = kk + (((lane >> 3) & 1) << 3);
            uint32_t off = sw128((uint32_t)(nrow*128 + kcol*2));
            uint32_t r0, r1, r2, r3;
            ldm_x4(r0, r1, r2, r3, bBase + off);
            b[g*2][0] = r0; b[g*2][1] = r1; b[g*2+1][0] = r2; b[g*2+1][1] = r3;
        }
#pragma unroll
        for (int mf = 0; mf < 4; mf++)
#pragma unroll
            for (int nf = 0; nf < 4; nf++)
                mma_bf16(acc[mf][nf], a[mf][0], a[mf][1], a[mf][2], a[mf][3],
                         b[nf][0], b[nf][1]);
    }
}

// ============================================================
// convert kw -> bf16 hi/lo
// ============================================================
__global__ void kwconv_kernel(const float* __restrict__ kw) {
    int n = HIDDEN*QDIM;
    for (int i = blockIdx.x*blockDim.x + threadIdx.x; i < n; i += gridDim.x*blockDim.x) {
        __nv_bfloat16 h, l; split_bf16(kw[i], h, l);
        g_kw_hi[i] = h; g_kw_lo[i] = l;
    }
}

// ============================================================
// convert + transpose k: [b][d][p] fp32 -> [b][p][d] bf16 hi/lo
// ============================================================
__global__ void kconv_kernel(const float* __restrict__ kin) {
    __shared__ float tile[32][33];
    int b = blockIdx.z;
    int p0 = blockIdx.x*32, d0 = blockIdx.y*32;
    int tx = threadIdx.x, ty = threadIdx.y;
    const float* src = kin + ((size_t)b*QDIM + d0)*NPIX + p0;
#pragma unroll
    for (int i = 0; i < 4; i++)
        tile[ty + i*8][tx] = src[(size_t)(ty + i*8)*NPIX + tx];
    __syncthreads();
#pragma unroll
    for (int i = 0; i < 4; i++) {
        int pl = ty + i*8;
        float x = tile[tx][pl];
        __nv_bfloat16 h, l; split_bf16(x, h, l);
        size_t o = ((size_t)b*NPIX + p0 + pl)*QDIM + d0 + tx;
        g_kt_hi[o] = h; g_kt_lo[o] = l;
    }
}

// ============================================================
// q projection (SIMT) -> qht hi/lo [b][n][f][c]
// ============================================================
__global__ void qproj_kernel(const float* __restrict__ q,
                             const float* __restrict__ qw,
                             const float* __restrict__ qb) {
    const int BM = 64, BN = 64, BK = 16;
    __shared__ float As[BK][BM];
    __shared__ float Bs[BK][BN];
    int t  = threadIdx.x;
    int tx = t & 15, ty = t >> 4;
    int m0 = blockIdx.y * BM;
    int n0 = blockIdx.x * BN;
    int lrow = t >> 2, lseg = t & 3;

    float acc[4][4] = {};
    for (int k0 = 0; k0 < QDIM; k0 += BK) {
        float4 av = make_float4(0.f, 0.f, 0.f, 0.f);
        int gm = m0 + lrow;
        if (gm < MROWS)
            av = *(const float4*)(q + (size_t)gm*QDIM + k0 + lseg*4);
        float4 bv = *(const float4*)(qw + (size_t)(n0 + lrow)*QDIM + k0 + lseg*4);
        __syncthreads();
        As[lseg*4+0][lrow]=av.x; As[lseg*4+1][lrow]=av.y;
        As[lseg*4+2][lrow]=av.z; As[lseg*4+3][lrow]=av.w;
        Bs[lseg*4+0][lrow]=bv.x; Bs[lseg*4+1][lrow]=bv.y;
        Bs[lseg*4+2][lrow]=bv.z; Bs[lseg*4+3][lrow]=bv.w;
        __syncthreads();
#pragma unroll
        for (int k = 0; k < BK; k++) {
            float a[4], b[4];
            *(float4*)a = *(float4*)&As[k][ty*4];
            *(float4*)b = *(float4*)&Bs[k][tx*4];
#pragma unroll
            for (int i = 0; i < 4; i++)
#pragma unroll
                for (int j = 0; j < 4; j++)
                    acc[i][j] += a[i]*b[j];
        }
    }
#pragma unroll
    for (int i = 0; i < 4; i++) {
        int gm = m0 + ty*4 + i;
        if (gm >= MROWS) continue;
        int b = gm / NFQ, f = gm % NFQ;
#pragma unroll
        for (int j = 0; j < 4; j++) {
            int e = n0 + tx*4 + j;
            int n = e >> 6, c = e & 63;
            float x = (acc[i][j] + qb[e]) * NORMF;
            __nv_bfloat16 h, l; split_bf16(x, h, l);
            size_t o = (((size_t)(b*NHEADS + n))*NFQ + f)*HD + c;
            g_qht_hi[o] = h; g_qht_lo[o] = l;
        }
    }
}

// ============================================================
// kproj HMMA: C[e,p] = sum_d kw[e,d]*kt[p,d] + kb[e]   (3-term split)
// -> transposed bf16 hi/lo kpt[b][head][p][c]
// grid (50 p, 4 e, 4 b), 256 thr
// ============================================================
__global__ void __launch_bounds__(256) kproj_mma_kernel(const float* __restrict__ kb) {
    extern __shared__ char smem[];
    uint32_t sb = smem_u32(smem);
    int t = threadIdx.x, lane = t & 31, w = t >> 5, wm = w >> 2, wn = w & 3;
    int b = blockIdx.z;
    int e0 = blockIdx.y * 128;
    int p0 = blockIdx.x * 128;

    float* kbs = (float*)(smem + KB_OFF);
    if (t < 128) kbs[t] = kb[e0 + t];

    const __nv_bfloat16* Apass[3] = { g_kw_hi, g_kw_lo, g_kw_hi };
    const __nv_bfloat16* Bpass[3] = { g_kt_hi, g_kt_hi, g_kt_lo };
    const __nv_bfloat16* Arow0[3];
    const __nv_bfloat16* Brow0[3];
#pragma unroll
    for (int pss = 0; pss < 3; pss++) {
        Arow0[pss] = Apass[pss] + (size_t)e0*QDIM;
        Brow0[pss] = Bpass[pss] + ((size_t)b*NPIX + p0)*QDIM;
    }

    float acc[4][4][4] = {};
    const int ITERS = 24;   // 3 passes * 8 chunks of 64

    // iteration 0 load
    {
        load_tile64(sb + STG_A0, Arow0[0], QDIM, 0, t, 128);
        load_tile64(sb + STG_B0, Brow0[0], QDIM, 0, t, 128);
        CP_COMMIT();
    }
    for (int it = 0; it < ITERS; it++) {
        if (it + 1 < ITERS) {
            int pss = (it+1) >> 3, k0 = ((it+1) & 7) * 64;
            uint32_t buf = ((it+1) & 1) ? STG_A1 : STG_A0;
            load_tile64(sb + buf,          Arow0[pss], QDIM, k0, t, 128);
            load_tile64(sb + buf + 16384u, Brow0[pss], QDIM, k0, t, 128);
            CP_COMMIT();
            CP_WAIT1();
        } else {
            CP_WAIT0();
        }
        __syncthreads();
        uint32_t buf = (it & 1) ? STG_A1 : STG_A0;
        compute_chunk(sb + buf, sb + buf + 16384u, wm, wn, lane, acc);
        __syncthreads();
    }

    // epilogue: frags -> smem fp32 [e][p] (+bias), then transposed bf16 split write
    float* Cs = (float*)(smem + C_OFF);
#pragma unroll
    for (int mf = 0; mf < 4; mf++) {
        int e = wm*64 + mf*16 + (lane >> 2);
        float b0 = kbs[e], b1 = kbs[e + 8];
#pragma unroll
        for (int nf = 0; nf < 4; nf++) {
            int p = wn*32 + nf*8 + (lane & 3)*2;
            Cs[e*132 + p]       = acc[mf][nf][0] + b0;
            Cs[e*132 + p + 1]   = acc[mf][nf][1] + b0;
            Cs[(e+8)*132 + p]   = acc[mf][nf][2] + b1;
            Cs[(e+8)*132 + p+1] = acc[mf][nf][3] + b1;
        }
    }
    __syncthreads();
    {
        int pl = t & 127, hd = t >> 7;     // hd in {0,1}: which head half of the 128 e rows
        size_t rowbase = (((size_t)(b*NHEADS) + blockIdx.y*2 + hd)*NPIX + p0 + pl)*HD;
#pragma unroll
        for (int c8 = 0; c8 < 8; c8++) {
            __align__(16) __nv_bfloat16 h8[8];
            __align__(16) __nv_bfloat16 l8[8];
#pragma unroll
            for (int j = 0; j < 8; j++) {
                float x = Cs[(hd*64 + c8*8 + j)*132 + pl];
                split_bf16(x, h8[j], l8[j]);
            }
            *(uint4*)(g_kpt_hi + rowbase + c8*8) = *(uint4*)h8;
            *(uint4*)(g_kpt_lo + rowbase + c8*8) = *(uint4*)l8;
        }
    }
}

// ============================================================
// scores HMMA: S[f,p] = sum_c qht[b,n,f,c]*kpt[b,n,p,c]  (3-term split)
// + mask + block softmax stats + store.  grid (50 p, 3 f, 32 bh)
// ============================================================
__global__ void __launch_bounds__(256) scores_mma_kernel(const int* __restrict__ mask,
                                                         float* __restrict__ out) {
    extern __shared__ char smem[];
    uint32_t sb = smem_u32(smem);
    int t = threadIdx.x, lane = t & 31, w = t >> 5, wm = w >> 2, wn = w & 3;
    int bh = blockIdx.z;
    int b = bh >> 3, n = bh & 7;
    int m0 = blockIdx.y * 128;
    int p0 = blockIdx.x * 128;

    int* mS = (int*)(smem + MK_OFF);
    if (t < 128) mS[t] = mask[(size_t)b*NPIX + p0 + t];

    int nrows = NFQ - m0; if (nrows > 128) nrows = 128;
    const __nv_bfloat16* Arow0[3] = {
        g_qht_hi + (((size_t)(b*NHEADS + n))*NFQ + m0)*HD,
        g_qht_lo + (((size_t)(b*NHEADS + n))*NFQ + m0)*HD,
        g_qht_hi + (((size_t)(b*NHEADS + n))*NFQ + m0)*HD };
    const __nv_bfloat16* Brow0[3] = {
        g_kpt_hi + (((size_t)(b*NHEADS + n))*NPIX + p0)*HD,
        g_kpt_hi + (((size_t)(b*NHEADS + n))*NPIX + p0)*HD,
        g_kpt_lo + (((size_t)(b*NHEADS + n))*NPIX + p0)*HD };

    float acc[4][4][4] = {};
    const int ITERS = 3;
    load_tile64(sb + STG_A0, Arow0[0], HD, 0, t, nrows);
    load_tile64(sb + STG_B0, Brow0[0], HD, 0, t, 128);
    CP_COMMIT();
    for (int it = 0; it < ITERS; it++) {
        if (it + 1 < ITERS) {
            uint32_t buf = ((it+1) & 1) ? STG_A1 : STG_A0;
            load_tile64(sb + buf,          Arow0[it+1], HD, 0, t, nrows);
            load_tile64(sb + buf + 16384u, Brow0[it+1], HD, 0, t, 128);
            CP_COMMIT();
            CP_WAIT1();
        } else {
            CP_WAIT0();
        }
        __syncthreads();
        uint32_t buf = (it & 1) ? STG_A1 : STG_A0;
        compute_chunk(sb + buf, sb + buf + 16384u, wm, wn, lane, acc);
        __syncthreads();
    }

    // ---- epilogue: mask + store + thread-local stats (from registers) ----
    float* rm = (float*)(smem + RM_OFF);
    float* rs = (float*)(smem + RS_OFF);
    size_t obase = (size_t)b*OROWS*NPIX;
    float tmax = -INFINITY;
#pragma unroll
    for (int mf = 0; mf < 4; mf++) {
        int fl = wm*64 + mf*16 + (lane >> 2);
#pragma unroll
        for (int half = 0; half < 2; half++) {
            int fg = m0 + fl + half*8;
            if (fg < NFQ) {
                size_t rowb = obase + ((size_t)fg*NHEADS + n)*NPIX + p0;
#pragma unroll
                for (int nf = 0; nf < 4; nf++) {
                    int nc = wn*32 + nf*8 + (lane & 3)*2;
                    float v0 = mS[nc]   ? -INFINITY : acc[mf][nf][half*2];
                    float v1 = mS[nc+1] ? -INFINITY : acc[mf][nf][half*2+1];
                    *(float2*)(out + rowb + nc) = make_float2(v0, v1);
                    tmax = fmaxf(tmax, fmaxf(v0, v1));
                }
            }
        }
    }
    float tsum = 0.f;
    if (tmax > -1e37f) {
#pragma unroll
        for (int mf = 0; mf < 4; mf++) {
            int fl = wm*64 + mf*16 + (lane >> 2);
#pragma unroll
            for (int half = 0; half < 2; half++) {
                int fg = m0 + fl + half*8;
                if (fg < NFQ) {
#pragma unroll
                    for (int nf = 0; nf < 4; nf++) {
                        int nc = wn*32 + nf*8 + (lane & 3)*2;
                        if (!mS[nc])   tsum += __expf(acc[mf][nf][half*2]   - tmax);
                        if (!mS[nc+1]) tsum += __expf(acc[mf][nf][half*2+1] - tmax);
                    }
                }
            }
        }
    }
    rm[t] = tmax; rs[t] = tsum;
    __syncthreads();
    for (int s = 128; s > 0; s >>= 1) {
        if (t < s) {
            float m1 = rm[t], s1v = rs[t];
            float m2 = rm[t+s], s2v = rs[t+s];
            float M = fmaxf(m1, m2);
            float sum = 0.f;
            if (m1 > -1e37f) sum += s1v * __expf(m1 - M);
            if (m2 > -1e37f) sum += s2v * __expf(m2 - M);
            rm[t] = M; rs[t] = sum;
        }
        __syncthreads();
    }
    if (t == 0) {
        int pidx = (int)blockIdx.z*150 + (int)blockIdx.y*50 + (int)blockIdx.x;
        g_pmax[pidx] = rm[0];
        g_psum[pidx] = rs[0];
    }
}

// ============================================================
// combine per-block stats -> per-batch (M, 1/Z)
// ============================================================
__global__ void combine_kernel() {
    __shared__ float rm[256];
    __shared__ float rs[256];
    int b = blockIdx.x, t = threadIdx.x;
    float m = -INFINITY, s = 0.f;
    for (int i = t; i < CBLK_PER_BATCH; i += 256) {
        float m2 = g_pmax[b*CBLK_PER_BATCH + i];
        float s2 = g_psum[b*CBLK_PER_BATCH + i];
        float M = fmaxf(m, m2);
        float ns = 0.f;
        if (m  > -1e37f) ns += s  * __expf(m  - M);
        if (m2 > -1e37f) ns += s2 * __expf(m2 - M);
        m = M; s = ns;
    }
    rm[t] = m; rs[t] = s;
    __syncthreads();
    for (int st = 128; st > 0; st >>= 1) {
        if (t < st) {
            float m1 = rm[t], s1v = rs[t];
            float m2 = rm[t+st], s2v = rs[t+st];
            float M = fmaxf(m1, m2);
            float sum = 0.f;
            if (m1 > -1e37f) sum += s1v * __expf(m1 - M);
            if (m2 > -1e37f) sum += s2v * __expf(m2 - M);
            rm[t] = M; rs[t] = sum;
        }
        __syncthreads();
    }
    if (t == 0) {
        g_M[b] = rm[0];
        g_invZ[b] = 1.0f / rs[0];
    }
}

// ============================================================
// normalize in place
// ============================================================
__global__ void norm_kernel(float* __restrict__ out) {
    const int VPB = (OROWS*NPIX) / 4;
    const int NV  = NBATCH * VPB;
    float4* o = (float4*)out;
    for (int i = blockIdx.x*blockDim.x + threadIdx.x; i < NV;
         i += gridDim.x*blockDim.x) {
        int b = i / VPB;
        float M  = g_M[b];
        float iz = g_invZ[b];
        float4 v = o[i];
        v.x = (v.x > -1e37f) ? __expf(v.x - M)*iz : 0.f;
        v.y = (v.y > -1e37f) ? __expf(v.y - M)*iz : 0.f;
        v.z = (v.z > -1e37f) ? __expf(v.z - M)*iz : 0.f;
        v.w = (v.w > -1e37f) ? __expf(v.w - M)*iz : 0.f;
        o[i] = v;
    }
}

// ============================================================
extern "C" void kernel_launch(void* const* d_in, const int* in_sizes, int n_in,
                              void* d_out, int out_size) {
    const float* q    = (const float*)d_in[0];
    const float* k    = (const float*)d_in[1];
    const int*   mask = (const int*)  d_in[2];
    const float* qw   = (const float*)d_in[3];
    const float* qb   = (const float*)d_in[4];
    const float* kw   = (const float*)d_in[5];
    const float* kb   = (const float*)d_in[6];
    float* out = (float*)d_out;

    // idempotent, non-allocating, capture-safe config calls (no static guards)
    cudaFuncSetAttribute(kproj_mma_kernel,  cudaFuncAttributeMaxDynamicSharedMemorySize, SMEM_SZ);
    cudaFuncSetAttribute(scores_mma_kernel, cudaFuncAttributeMaxDynamicSharedMemorySize, SMEM_SZ);

    kwconv_kernel <<<256, 256>>>(kw);
    kconv_kernel  <<<dim3(200, 16, 4), dim3(32, 8)>>>(k);
    qproj_kernel  <<<dim3(8, 19), 256>>>(q, qw, qb);
    kproj_mma_kernel <<<dim3(50, 4, 4),  256, SMEM_SZ>>>(kb);
    scores_mma_kernel<<<dim3(50, 3, 32), 256, SMEM_SZ>>>(mask, out);
    combine_kernel<<<4, 256>>>();
    norm_kernel   <<<2048, 256>>>(out);
}

// round 7
// speedup vs baseline: 2.7896x; 1.0038x over previous
#include <cuda_runtime.h>
#include <cuda_bf16.h>
#include <stdint.h>
#include <math.h>

#define NBATCH 4
#define NFQ    300
#define QDIM   512
#define HIDDEN 512
#define NHEADS 8
#define HD     64
#define NPIX   6400
#define NORMF  0.125f
#define MROWS  (NBATCH*NFQ)          // 1200
#define OROWS  (NFQ*NHEADS)          // 2400
#define CBLK_PER_BATCH 1200          // 8 heads * 3 mtiles * 50 ntiles

// ---------------- static device scratch ----------------
__device__ __nv_bfloat16 g_kw_hi[HIDDEN*QDIM];
__device__ __nv_bfloat16 g_kw_lo[HIDDEN*QDIM];
__device__ __nv_bfloat16 g_kt_hi[(size_t)NBATCH*NPIX*QDIM];   // [b][p][d]
__device__ __nv_bfloat16 g_kt_lo[(size_t)NBATCH*NPIX*QDIM];
__device__ __nv_bfloat16 g_qht_hi[NBATCH*NHEADS*NFQ*HD];      // [b][n][f][c]
__device__ __nv_bfloat16 g_qht_lo[NBATCH*NHEADS*NFQ*HD];
__device__ __nv_bfloat16 g_kpt_hi[(size_t)NBATCH*NHEADS*NPIX*HD]; // [b][n][p][c]
__device__ __nv_bfloat16 g_kpt_lo[(size_t)NBATCH*NHEADS*NPIX*HD];
__device__ float g_pmax[NBATCH*CBLK_PER_BATCH];
__device__ float g_psum[NBATCH*CBLK_PER_BATCH];
__device__ float g_M[NBATCH];
__device__ float g_invZ[NBATCH];

// ---------------- smem layout (bytes into dynamic smem) ----------------
// 3 stages, each: A tile 16KB + B tile 16KB = 32KB
#define STAGE_SZ 32768u
#define STG(s)   ((uint32_t)(s) * STAGE_SZ)
#define C_OFF  0u                        // fp32 [128][132] overlay after compute: 67584 B
#define KB_OFF 98304u                    // kproj: bias tile (512 B)
#define RM_OFF 98304u                    // scores: reduce max (1024 B)
#define RS_OFF 99328u                    // scores: reduce sum (1024 B)
#define MK_OFF 100352u                   // scores: mask tile (512 B)
#define SMEM_SZ 100864u

// ---------------- ptx helpers ----------------
__device__ __forceinline__ uint32_t smem_u32(const void* p) {
    uint32_t a;
    asm("{ .reg .u64 t; cvta.to.shared.u64 t, %1; cvt.u32.u64 %0, t; }" : "=r"(a) : "l"(p));
    return a;
}
__device__ __forceinline__ void cpa16(uint32_t dst, const void* src, int srcbytes) {
    asm volatile("cp.async.cg.shared.global [%0], [%1], 16, %2;"
                 :: "r"(dst), "l"(src), "r"(srcbytes) : "memory");
}
#define CP_COMMIT() asm volatile("cp.async.commit_group;" ::: "memory")
#define CP_WAIT1()  asm volatile("cp.async.wait_group 1;" ::: "memory")
#define CP_WAIT0()  asm volatile("cp.async.wait_group 0;" ::: "memory")

__device__ __forceinline__ void ldm_x4(uint32_t& r0, uint32_t& r1, uint32_t& r2, uint32_t& r3,
                                       uint32_t addr) {
    asm volatile("ldmatrix.sync.aligned.m8n8.x4.shared.b16 {%0,%1,%2,%3}, [%4];"
                 : "=r"(r0), "=r"(r1), "=r"(r2), "=r"(r3) : "r"(addr));
}
__device__ __forceinline__ void mma_bf16(float* c, uint32_t a0, uint32_t a1, uint32_t a2,
                                         uint32_t a3, uint32_t b0, uint32_t b1) {
    asm volatile("mma.sync.aligned.m16n8k16.row.col.f32.bf16.bf16.f32 "
        "{%0,%1,%2,%3}, {%4,%5,%6,%7}, {%8,%9}, {%0,%1,%2,%3};"
        : "+f"(c[0]), "+f"(c[1]), "+f"(c[2]), "+f"(c[3])
        : "r"(a0), "r"(a1), "r"(a2), "r"(a3), "r"(b0), "r"(b1));
}
__device__ __forceinline__ uint32_t sw128(uint32_t off) { return off ^ ((off >> 3) & 0x70); }

__device__ __forceinline__ void split_bf16(float x, __nv_bfloat16& h, __nv_bfloat16& l) {
    h = __float2bfloat16(x);
    l = __float2bfloat16(x - __bfloat162float(h));
}

// ---- load a [128 rows x 64 bf16] tile into swizzled smem via cp.async ----
__device__ __forceinline__ void load_tile64(uint32_t dst, const __nv_bfloat16* base,
                                            int rowstride, int k0, int t, int nrows) {
    int r = t >> 1, half = t & 1;
    int rc = (r < nrows) ? r : 0;
    const char* src = (const char*)(base + (size_t)rc*rowstride + k0 + half*32);
    int ok = (r < nrows) ? 16 : 0;
#pragma unroll
    for (int j = 0; j < 4; j++) {
        uint32_t off = sw128((uint32_t)(r*128 + half*64 + j*16));
        cpa16(dst + off, src + j*16, ok);
    }
}

// ---- one 64-wide K chunk of 128x128 HMMA (warp tile 64x32) ----
__device__ __forceinline__ void compute_chunk(uint32_t aBase, uint32_t bBase,
                                              int wm, int wn, int lane,
                                              float acc[4][4][4]) {
#pragma unroll
    for (int kk = 0; kk < 64; kk += 16) {
        uint32_t a[4][4];
#pragma unroll
        for (int mf = 0; mf < 4; mf++) {
            int row  = wm*64 + mf*16 + (lane & 15);
            int kcol = kk + ((lane >> 4) << 3);
            uint32_t off = sw128((uint32_t)(row*128 + kcol*2));
            ldm_x4(a[mf][0], a[mf][1], a[mf][2], a[mf][3], aBase + off);
        }
        uint32_t b[4][2];
#pragma unroll
        for (int g = 0; g < 2; g++) {
            int nrow = wn*32 + g*16 + ((lane >> 4) << 3) + (lane & 7);
            int kcol = kk + (((lane >> 3) & 1) << 3);
            uint32_t off = sw128((uint32_t)(nrow*128 + kcol*2));
            uint32_t r0, r1, r2, r3;
            ldm_x4(r0, r1, r2, r3, bBase + off);
            b[g*2][0] = r0; b[g*2][1] = r1; b[g*2+1][0] = r2; b[g*2+1][1] = r3;
        }
#pragma unroll
        for (int mf = 0; mf < 4; mf++)
#pragma unroll
            for (int nf = 0; nf < 4; nf++)
                mma_bf16(acc[mf][nf], a[mf][0], a[mf][1], a[mf][2], a[mf][3],
                         b[nf][0], b[nf][1]);
    }
}

// ============================================================
// convert kw -> bf16 hi/lo
// ============================================================
__global__ void kwconv_kernel(const float* __restrict__ kw) {
    int n = HIDDEN*QDIM;
    for (int i = blockIdx.x*blockDim.x + threadIdx.x; i < n; i += gridDim.x*blockDim.x) {
        __nv_bfloat16 h, l; split_bf16(kw[i], h, l);
        g_kw_hi[i] = h; g_kw_lo[i] = l;
    }
}

// ============================================================
// convert + transpose k: [b][d][p] fp32 -> [b][p][d] bf16 hi/lo
// ============================================================
__global__ void kconv_kernel(const float* __restrict__ kin) {
    __shared__ float tile[32][33];
    int b = blockIdx.z;
    int p0 = blockIdx.x*32, d0 = blockIdx.y*32;
    int tx = threadIdx.x, ty = threadIdx.y;
    const float* src = kin + ((size_t)b*QDIM + d0)*NPIX + p0;
#pragma unroll
    for (int i = 0; i < 4; i++)
        tile[ty + i*8][tx] = src[(size_t)(ty + i*8)*NPIX + tx];
    __syncthreads();
#pragma unroll
    for (int i = 0; i < 4; i++) {
        int pl = ty + i*8;
        float x = tile[tx][pl];
        __nv_bfloat16 h, l; split_bf16(x, h, l);
        size_t o = ((size_t)b*NPIX + p0 + pl)*QDIM + d0 + tx;
        g_kt_hi[o] = h; g_kt_lo[o] = l;
    }
}

// ============================================================
// q projection (SIMT) -> qht hi/lo [b][n][f][c]
// ============================================================
__global__ void qproj_kernel(const float* __restrict__ q,
                             const float* __restrict__ qw,
                             const float* __restrict__ qb) {
    const int BM = 64, BN = 64, BK = 16;
    __shared__ float As[BK][BM];
    __shared__ float Bs[BK][BN];
    int t  = threadIdx.x;
    int tx = t & 15, ty = t >> 4;
    int m0 = blockIdx.y * BM;
    int n0 = blockIdx.x * BN;
    int lrow = t >> 2, lseg = t & 3;

    float acc[4][4] = {};
    for (int k0 = 0; k0 < QDIM; k0 += BK) {
        float4 av = make_float4(0.f, 0.f, 0.f, 0.f);
        int gm = m0 + lrow;
        if (gm < MROWS)
            av = *(const float4*)(q + (size_t)gm*QDIM + k0 + lseg*4);
        float4 bv = *(const float4*)(qw + (size_t)(n0 + lrow)*QDIM + k0 + lseg*4);
        __syncthreads();
        As[lseg*4+0][lrow]=av.x; As[lseg*4+1][lrow]=av.y;
        As[lseg*4+2][lrow]=av.z; As[lseg*4+3][lrow]=av.w;
        Bs[lseg*4+0][lrow]=bv.x; Bs[lseg*4+1][lrow]=bv.y;
        Bs[lseg*4+2][lrow]=bv.z; Bs[lseg*4+3][lrow]=bv.w;
        __syncthreads();
#pragma unroll
        for (int k = 0; k < BK; k++) {
            float a[4], b[4];
            *(float4*)a = *(float4*)&As[k][ty*4];
            *(float4*)b = *(float4*)&Bs[k][tx*4];
#pragma unroll
            for (int i = 0; i < 4; i++)
#pragma unroll
                for (int j = 0; j < 4; j++)
                    acc[i][j] += a[i]*b[j];
        }
    }
#pragma unroll
    for (int i = 0; i < 4; i++) {
        int gm = m0 + ty*4 + i;
        if (gm >= MROWS) continue;
        int b = gm / NFQ, f = gm % NFQ;
#pragma unroll
        for (int j = 0; j < 4; j++) {
            int e = n0 + tx*4 + j;
            int n = e >> 6, c = e & 63;
            float x = (acc[i][j] + qb[e]) * NORMF;
            __nv_bfloat16 h, l; split_bf16(x, h, l);
            size_t o = (((size_t)(b*NHEADS + n))*NFQ + f)*HD + c;
            g_qht_hi[o] = h; g_qht_lo[o] = l;
        }
    }
}

// ============================================================
// kproj HMMA (3-stage pipeline): C[e,p] = sum_d kw[e,d]*kt[p,d] + kb[e]
// -> transposed bf16 hi/lo kpt[b][head][p][c]
// grid (50 p, 4 e, 4 b), 256 thr
// ============================================================
__global__ void __launch_bounds__(256, 2) kproj_mma_kernel(const float* __restrict__ kb) {
    extern __shared__ char smem[];
    uint32_t sb = smem_u32(smem);
    int t = threadIdx.x, lane = t & 31, w = t >> 5, wm = w >> 2, wn = w & 3;
    int b = blockIdx.z;
    int e0 = blockIdx.y * 128;
    int p0 = blockIdx.x * 128;

    const __nv_bfloat16* Arow0[3];
    const __nv_bfloat16* Brow0[3];
    {
        const __nv_bfloat16* Apass[3] = { g_kw_hi, g_kw_lo, g_kw_hi };
        const __nv_bfloat16* Bpass[3] = { g_kt_hi, g_kt_hi, g_kt_lo };
#pragma unroll
        for (int pss = 0; pss < 3; pss++) {
            Arow0[pss] = Apass[pss] + (size_t)e0*QDIM;
            Brow0[pss] = Bpass[pss] + ((size_t)b*NPIX + p0)*QDIM;
        }
    }

    float acc[4][4][4] = {};
    const int ITERS = 24;   // 3 passes * 8 chunks of 64

    // prologue: stages 0, 1
    load_tile64(sb + STG(0),          Arow0[0], QDIM, 0, t, 128);
    load_tile64(sb + STG(0) + 16384u, Brow0[0], QDIM, 0, t, 128);
    CP_COMMIT();
    load_tile64(sb + STG(1),          Arow0[0], QDIM, 64, t, 128);
    load_tile64(sb + STG(1) + 16384u, Brow0[0], QDIM, 64, t, 128);
    CP_COMMIT();

    int stage = 0, nstage = 2;
    for (int it = 0; it < ITERS; it++) {
        if (it == ITERS - 1) { CP_WAIT0(); } else { CP_WAIT1(); }
        __syncthreads();
        if (it + 2 < ITERS) {
            int pss = (it+2) >> 3, k0 = ((it+2) & 7) * 64;
            load_tile64(sb + STG(nstage),          Arow0[pss], QDIM, k0, t, 128);
            load_tile64(sb + STG(nstage) + 16384u, Brow0[pss], QDIM, k0, t, 128);
            CP_COMMIT();
        }
        compute_chunk(sb + STG(stage), sb + STG(stage) + 16384u, wm, wn, lane, acc);
        stage = (stage + 1 == 3) ? 0 : stage + 1;
        nstage = (nstage + 1 == 3) ? 0 : nstage + 1;
    }
    __syncthreads();   // protect C overlay (aliases stage buffers)

    // epilogue: frags -> smem fp32 [e][p] (+bias), then transposed bf16 split write
    float* Cs = (float*)(smem + C_OFF);
    float* kbs = (float*)(smem + KB_OFF);
    if (t < 128) kbs[t] = kb[e0 + t];
    __syncthreads();
#pragma unroll
    for (int mf = 0; mf < 4; mf++) {
        int e = wm*64 + mf*16 + (lane >> 2);
        float b0 = kbs[e], b1 = kbs[e + 8];
#pragma unroll
        for (int nf = 0; nf < 4; nf++) {
            int p = wn*32 + nf*8 + (lane & 3)*2;
            Cs[e*132 + p]       = acc[mf][nf][0] + b0;
            Cs[e*132 + p + 1]   = acc[mf][nf][1] + b0;
            Cs[(e+8)*132 + p]   = acc[mf][nf][2] + b1;
            Cs[(e+8)*132 + p+1] = acc[mf][nf][3] + b1;
        }
    }
    __syncthreads();
    {
        int pl = t & 127, hd = t >> 7;     // hd in {0,1}: which head half of the 128 e rows
        size_t rowbase = (((size_t)(b*NHEADS) + blockIdx.y*2 + hd)*NPIX + p0 + pl)*HD;
#pragma unroll
        for (int c8 = 0; c8 < 8; c8++) {
            __align__(16) __nv_bfloat16 h8[8];
            __align__(16) __nv_bfloat16 l8[8];
#pragma unroll
            for (int j = 0; j < 8; j++) {
                float x = Cs[(hd*64 + c8*8 + j)*132 + pl];
                split_bf16(x, h8[j], l8[j]);
            }
            *(uint4*)(g_kpt_hi + rowbase + c8*8) = *(uint4*)h8;
            *(uint4*)(g_kpt_lo + rowbase + c8*8) = *(uint4*)l8;
        }
    }
}

// ============================================================
// scores HMMA (3-stage, fully prefetched): S[f,p] = sum_c qht·kpt
// + mask + block softmax stats + store.  grid (50 p, 3 f, 32 bh)
// ============================================================
__global__ void __launch_bounds__(256, 2) scores_mma_kernel(const int* __restrict__ mask,
                                                            float* __restrict__ out) {
    extern __shared__ char smem[];
    uint32_t sb = smem_u32(smem);
    int t = threadIdx.x, lane = t & 31, w = t >> 5, wm = w >> 2, wn = w & 3;
    int bh = blockIdx.z;
    int b = bh >> 3, n = bh & 7;
    int m0 = blockIdx.y * 128;
    int p0 = blockIdx.x * 128;

    int* mS = (int*)(smem + MK_OFF);
    if (t < 128) mS[t] = mask[(size_t)b*NPIX + p0 + t];

    int nrows = NFQ - m0; if (nrows > 128) nrows = 128;
    const __nv_bfloat16* Arow0[3] = {
        g_qht_hi + (((size_t)(b*NHEADS + n))*NFQ + m0)*HD,
        g_qht_lo + (((size_t)(b*NHEADS + n))*NFQ + m0)*HD,
        g_qht_hi + (((size_t)(b*NHEADS + n))*NFQ + m0)*HD };
    const __nv_bfloat16* Brow0[3] = {
        g_kpt_hi + (((size_t)(b*NHEADS + n))*NPIX + p0)*HD,
        g_kpt_hi + (((size_t)(b*NHEADS + n))*NPIX + p0)*HD,
        g_kpt_lo + (((size_t)(b*NHEADS + n))*NPIX + p0)*HD };

    float acc[4][4][4] = {};
    const int ITERS = 3;
    load_tile64(sb + STG(0),          Arow0[0], HD, 0, t, nrows);
    load_tile64(sb + STG(0) + 16384u, Brow0[0], HD, 0, t, 128);
    CP_COMMIT();
    load_tile64(sb + STG(1),          Arow0[1], HD, 0, t, nrows);
    load_tile64(sb + STG(1) + 16384u, Brow0[1], HD, 0, t, 128);
    CP_COMMIT();
    for (int it = 0; it < ITERS; it++) {
        if (it == ITERS - 1) { CP_WAIT0(); } else { CP_WAIT1(); }
        __syncthreads();
        if (it + 2 < ITERS) {
            load_tile64(sb + STG(2),          Arow0[2], HD, 0, t, nrows);
            load_tile64(sb + STG(2) + 16384u, Brow0[2], HD, 0, t, 128);
            CP_COMMIT();
        }
        compute_chunk(sb + STG(it), sb + STG(it) + 16384u, wm, wn, lane, acc);
    }

    // ---- epilogue: mask + store + thread-local stats (from registers) ----
    float* rm = (float*)(smem + RM_OFF);
    float* rs = (float*)(smem + RS_OFF);
    size_t obase = (size_t)b*OROWS*NPIX;
    float tmax = -INFINITY;
#pragma unroll
    for (int mf = 0; mf < 4; mf++) {
        int fl = wm*64 + mf*16 + (lane >> 2);
#pragma unroll
        for (int half = 0; half < 2; half++) {
            int fg = m0 + fl + half*8;
            if (fg < NFQ) {
                size_t rowb = obase + ((size_t)fg*NHEADS + n)*NPIX + p0;
#pragma unroll
                for (int nf = 0; nf < 4; nf++) {
                    int nc = wn*32 + nf*8 + (lane & 3)*2;
                    float v0 = mS[nc]   ? -INFINITY : acc[mf][nf][half*2];
                    float v1 = mS[nc+1] ? -INFINITY : acc[mf][nf][half*2+1];
                    *(float2*)(out + rowb + nc) = make_float2(v0, v1);
                    tmax = fmaxf(tmax, fmaxf(v0, v1));
                }
            }
        }
    }
    float tsum = 0.f;
    if (tmax > -1e37f) {
#pragma unroll
        for (int mf = 0; mf < 4; mf++) {
            int fl = wm*64 + mf*16 + (lane >> 2);
#pragma unroll
            for (int half = 0; half < 2; half++) {
                int fg = m0 + fl + half*8;
                if (fg < NFQ) {
#pragma unroll
                    for (int nf = 0; nf < 4; nf++) {
                        int nc = wn*32 + nf*8 + (lane & 3)*2;
                        if (!mS[nc])   tsum += __expf(acc[mf][nf][half*2]   - tmax);
                        if (!mS[nc+1]) tsum += __expf(acc[mf][nf][half*2+1] - tmax);
                    }
                }
            }
        }
    }
    rm[t] = tmax; rs[t] = tsum;
    __syncthreads();
    for (int s = 128; s > 0; s >>= 1) {
        if (t < s) {
            float m1 = rm[t], s1v = rs[t];
            float m2 = rm[t+s], s2v = rs[t+s];
            float M = fmaxf(m1, m2);
            float sum = 0.f;
            if (m1 > -1e37f) sum += s1v * __expf(m1 - M);
            if (m2 > -1e37f) sum += s2v * __expf(m2 - M);
            rm[t] = M; rs[t] = sum;
        }
        __syncthreads();
    }
    if (t == 0) {
        int pidx = (int)blockIdx.z*150 + (int)blockIdx.y*50 + (int)blockIdx.x;
        g_pmax[pidx] = rm[0];
        g_psum[pidx] = rs[0];
    }
}

// ============================================================
// combine per-block stats -> per-batch (M, 1/Z)
// ============================================================
__global__ void combine_kernel() {
    __shared__ float rm[256];
    __shared__ float rs[256];
    int b = blockIdx.x, t = threadIdx.x;
    float m = -INFINITY, s = 0.f;
    for (int i = t; i < CBLK_PER_BATCH; i += 256) {
        float m2 = g_pmax[b*CBLK_PER_BATCH + i];
        float s2 = g_psum[b*CBLK_PER_BATCH + i];
        float M = fmaxf(m, m2);
        float ns = 0.f;
        if (m  > -1e37f) ns += s  * __expf(m  - M);
        if (m2 > -1e37f) ns += s2 * __expf(m2 - M);
        m = M; s = ns;
    }
    rm[t] = m; rs[t] = s;
    __syncthreads();
    for (int st = 128; st > 0; st >>= 1) {
        if (t < st) {
            float m1 = rm[t], s1v = rs[t];
            float m2 = rm[t+st], s2v = rs[t+st];
            float M = fmaxf(m1, m2);
            float sum = 0.f;
            if (m1 > -1e37f) sum += s1v * __expf(m1 - M);
            if (m2 > -1e37f) sum += s2v * __expf(m2 - M);
            rm[t] = M; rs[t] = sum;
        }
        __syncthreads();
    }
    if (t == 0) {
        g_M[b] = rm[0];
        g_invZ[b] = 1.0f / rs[0];
    }
}

// ============================================================
// normalize in place
// ============================================================
__global__ void norm_kernel(float* __restrict__ out) {
    const int VPB = (OROWS*NPIX) / 4;
    const int NV  = NBATCH * VPB;
    float4* o = (float4*)out;
    for (int i = blockIdx.x*blockDim.x + threadIdx.x; i < NV;
         i += gridDim.x*blockDim.x) {
        int b = i / VPB;
        float M  = g_M[b];
        float iz = g_invZ[b];
        float4 v = o[i];
        v.x = (v.x > -1e37f) ? __expf(v.x - M)*iz : 0.f;
        v.y = (v.y > -1e37f) ? __expf(v.y - M)*iz : 0.f;
        v.z = (v.z > -1e37f) ? __expf(v.z - M)*iz : 0.f;
        v.w = (v.w > -1e37f) ? __expf(v.w - M)*iz : 0.f;
        o[i] = v;
    }
}

// ============================================================
extern "C" void kernel_launch(void* const* d_in, const int* in_sizes, int n_in,
                              void* d_out, int out_size) {
    const float* q    = (const float*)d_in[0];
    const float* k    = (const float*)d_in[1];
    const int*   mask = (const int*)  d_in[2];
    const float* qw   = (const float*)d_in[3];
    const float* qb   = (const float*)d_in[4];
    const float* kw   = (const float*)d_in[5];
    const float* kb   = (const float*)d_in[6];
    float* out = (float*)d_out;

    cudaFuncSetAttribute(kproj_mma_kernel,  cudaFuncAttributeMaxDynamicSharedMemorySize, SMEM_SZ);
    cudaFuncSetAttribute(scores_mma_kernel, cudaFuncAttributeMaxDynamicSharedMemorySize, SMEM_SZ);

    kwconv_kernel <<<256, 256>>>(kw);
    kconv_kernel  <<<dim3(200, 16, 4), dim3(32, 8)>>>(k);
    qproj_kernel  <<<dim3(8, 19), 256>>>(q, qw, qb);
    kproj_mma_kernel <<<dim3(50, 4, 4),  256, SMEM_SZ>>>(kb);
    scores_mma_kernel<<<dim3(50, 3, 32), 256, SMEM_SZ>>>(mask, out);
    combine_kernel<<<4, 256>>>();
    norm_kernel   <<<2048, 256>>>(out);
}